// round 1
// baseline (speedup 1.0000x reference)
#include <cuda_runtime.h>
#include <math.h>

#define EMBED 1024
#define HEAD  128
#define BATCH 8
#define SEQ   2048
#define MTOT  (BATCH*SEQ)

// Scratch for Q/K/V projections (allocation-free: __device__ globals).
__device__ float g_q[MTOT * HEAD];
__device__ float g_k[MTOT * HEAD];
__device__ float g_v[MTOT * HEAD];

// ---------------------------------------------------------------------------
// Kernel A: fused QKV projection.  out[z] = x @ W[z],  x:[16384,1024], W:[1024,128]
// Block tile 64x128, K-chunk 32, 256 threads, 4x8 micro-tile.
// Column mapping col = tx + cc*16 -> conflict-free Ws reads, coalesced stores.
// ---------------------------------------------------------------------------
__global__ __launch_bounds__(256) void qkv_proj(
    const float* __restrict__ x,
    const float* __restrict__ Wq,
    const float* __restrict__ Wk,
    const float* __restrict__ Wv)
{
    __shared__ float Xs[64][32];
    __shared__ float Ws[32][128];

    const float* W   = (blockIdx.z == 0) ? Wq : (blockIdx.z == 1) ? Wk : Wv;
    float*       out = (blockIdx.z == 0) ? g_q : (blockIdx.z == 1) ? g_k : g_v;

    const int tid = threadIdx.x;
    const int tx  = tid & 15;
    const int ty  = tid >> 4;
    const int m0  = blockIdx.x * 64;

    float acc[4][8];
#pragma unroll
    for (int r = 0; r < 4; r++)
#pragma unroll
        for (int c = 0; c < 8; c++) acc[r][c] = 0.f;

    for (int k0 = 0; k0 < EMBED; k0 += 32) {
        // X tile: 64x32 = 512 float4, 2 per thread
#pragma unroll
        for (int t = 0; t < 2; t++) {
            int i = tid + t * 256;
            int row = i >> 3, c4 = i & 7;
            float4 xv = *reinterpret_cast<const float4*>(
                &x[(size_t)(m0 + row) * EMBED + k0 + c4 * 4]);
            *reinterpret_cast<float4*>(&Xs[row][c4 * 4]) = xv;
        }
        // W tile: 32x128 = 1024 float4, 4 per thread
#pragma unroll
        for (int t = 0; t < 4; t++) {
            int i = tid + t * 256;
            int row = i >> 5, c4 = i & 31;
            float4 wv = *reinterpret_cast<const float4*>(
                &W[(size_t)(k0 + row) * HEAD + c4 * 4]);
            *reinterpret_cast<float4*>(&Ws[row][c4 * 4]) = wv;
        }
        __syncthreads();

#pragma unroll
        for (int kk = 0; kk < 32; kk++) {
            float a[4], bfr[8];
#pragma unroll
            for (int r = 0; r < 4; r++) a[r] = Xs[ty * 4 + r][kk];
#pragma unroll
            for (int c = 0; c < 8; c++) bfr[c] = Ws[kk][tx + c * 16];
#pragma unroll
            for (int r = 0; r < 4; r++)
#pragma unroll
                for (int c = 0; c < 8; c++) acc[r][c] = fmaf(a[r], bfr[c], acc[r][c]);
        }
        __syncthreads();
    }

#pragma unroll
    for (int r = 0; r < 4; r++)
#pragma unroll
        for (int c = 0; c < 8; c++)
            out[(size_t)(m0 + ty * 4 + r) * HEAD + tx + c * 16] = acc[r][c];
}

// ---------------------------------------------------------------------------
// Kernel B: flash attention (causal, scale 1/sqrt(EMBED) = 1/32).
// BM=BN=64, H=128 in smem, pad stride 129. 256 threads:
//   rows r = ty*4 + rr (4 per thread), cols c = tx + cc*16.
// Online softmax: shfl_xor reductions over the 16-lane tx group.
// ---------------------------------------------------------------------------
#define BM 64
#define BN 64
#define KSTR 129
#define PSTR 65
#define FA_SMEM ((3 * BM * KSTR + BM * PSTR) * (int)sizeof(float))

__global__ __launch_bounds__(256) void flash_attn(float* __restrict__ out)
{
    extern __shared__ float sm[];
    float* Qs = sm;                       // 64*129
    float* Ks = Qs + BM * KSTR;           // 64*129
    float* Vs = Ks + BM * KSTR;           // 64*129
    float* Ps = Vs + BM * KSTR;           // 64*65

    const int tid = threadIdx.x;
    const int tx  = tid & 15;
    const int ty  = tid >> 4;
    const int qt  = blockIdx.x;           // query tile index (0..31)
    const int b   = blockIdx.y;           // batch
    const int q0  = qt * BM;

    // Load Q tile (64x128) once
    const float* qbase = g_q + ((size_t)b * SEQ + q0) * HEAD;
#pragma unroll
    for (int t = 0; t < 8; t++) {
        int i = tid + t * 256;
        int row = i >> 5, c4 = i & 31;
        float4 v = *reinterpret_cast<const float4*>(&qbase[(size_t)row * HEAD + c4 * 4]);
        float* dst = &Qs[row * KSTR + c4 * 4];
        dst[0] = v.x; dst[1] = v.y; dst[2] = v.z; dst[3] = v.w;
    }

    float acc[4][8];
    float mrow[4], lrow[4];
#pragma unroll
    for (int r = 0; r < 4; r++) {
        mrow[r] = -INFINITY;
        lrow[r] = 0.f;
#pragma unroll
        for (int c = 0; c < 8; c++) acc[r][c] = 0.f;
    }

    const float scale = 0.03125f;  // 1/sqrt(1024)

    for (int kt = 0; kt <= qt; kt++) {
        __syncthreads();  // Q visible (iter 0); prev-iter Ps/Vs reads done before overwrite
        const int k0 = kt * BN;
        const float* kbase = g_k + ((size_t)b * SEQ + k0) * HEAD;
        const float* vbase = g_v + ((size_t)b * SEQ + k0) * HEAD;
#pragma unroll
        for (int t = 0; t < 8; t++) {
            int i = tid + t * 256;
            int row = i >> 5, c4 = i & 31;
            float4 kv = *reinterpret_cast<const float4*>(&kbase[(size_t)row * HEAD + c4 * 4]);
            float* kd = &Ks[row * KSTR + c4 * 4];
            kd[0] = kv.x; kd[1] = kv.y; kd[2] = kv.z; kd[3] = kv.w;
            float4 vv = *reinterpret_cast<const float4*>(&vbase[(size_t)row * HEAD + c4 * 4]);
            float* vd = &Vs[row * KSTR + c4 * 4];
            vd[0] = vv.x; vd[1] = vv.y; vd[2] = vv.z; vd[3] = vv.w;
        }
        __syncthreads();

        // S = Q * K^T  (64x64, 4x4 per thread)
        float s[4][4];
#pragma unroll
        for (int r = 0; r < 4; r++)
#pragma unroll
            for (int c = 0; c < 4; c++) s[r][c] = 0.f;

#pragma unroll 4
        for (int h = 0; h < HEAD; h++) {
            float qf[4], kf[4];
#pragma unroll
            for (int r = 0; r < 4; r++) qf[r] = Qs[(ty * 4 + r) * KSTR + h];
#pragma unroll
            for (int c = 0; c < 4; c++) kf[c] = Ks[(tx + c * 16) * KSTR + h];
#pragma unroll
            for (int r = 0; r < 4; r++)
#pragma unroll
                for (int c = 0; c < 4; c++) s[r][c] = fmaf(qf[r], kf[c], s[r][c]);
        }

        // scale + causal mask (only needed on the diagonal tile)
        if (kt == qt) {
#pragma unroll
            for (int r = 0; r < 4; r++) {
                int ri = ty * 4 + r;
#pragma unroll
                for (int c = 0; c < 4; c++) {
                    int cj = tx + c * 16;
                    s[r][c] = (cj > ri) ? -INFINITY : s[r][c] * scale;
                }
            }
        } else {
#pragma unroll
            for (int r = 0; r < 4; r++)
#pragma unroll
                for (int c = 0; c < 4; c++) s[r][c] *= scale;
        }

        // Online softmax per row
#pragma unroll
        for (int r = 0; r < 4; r++) {
            float tmax = s[r][0];
#pragma unroll
            for (int c = 1; c < 4; c++) tmax = fmaxf(tmax, s[r][c]);
#pragma unroll
            for (int off = 8; off >= 1; off >>= 1)
                tmax = fmaxf(tmax, __shfl_xor_sync(0xffffffffu, tmax, off));

            float mnew = fmaxf(mrow[r], tmax);
            float corr = __expf(mrow[r] - mnew);
            float p[4], rs = 0.f;
#pragma unroll
            for (int c = 0; c < 4; c++) { p[c] = __expf(s[r][c] - mnew); rs += p[c]; }
#pragma unroll
            for (int off = 8; off >= 1; off >>= 1)
                rs += __shfl_xor_sync(0xffffffffu, rs, off);

            lrow[r] = lrow[r] * corr + rs;
            mrow[r] = mnew;
#pragma unroll
            for (int c = 0; c < 8; c++) acc[r][c] *= corr;
#pragma unroll
            for (int c = 0; c < 4; c++) Ps[(ty * 4 + r) * PSTR + tx + c * 16] = p[c];
        }
        __syncthreads();

        // O += P * V   (64x128, 4x8 per thread)
#pragma unroll 4
        for (int j = 0; j < BN; j++) {
            float vf[8];
#pragma unroll
            for (int c = 0; c < 8; c++) vf[c] = Vs[j * KSTR + tx + c * 16];
#pragma unroll
            for (int r = 0; r < 4; r++) {
                float pj = Ps[(ty * 4 + r) * PSTR + j];
#pragma unroll
                for (int c = 0; c < 8; c++) acc[r][c] = fmaf(pj, vf[c], acc[r][c]);
            }
        }
    }

    // Epilogue: normalize and store
    float* obase = out + ((size_t)b * SEQ + q0) * HEAD;
#pragma unroll
    for (int r = 0; r < 4; r++) {
        float inv = 1.f / lrow[r];
#pragma unroll
        for (int c = 0; c < 8; c++)
            obase[(size_t)(ty * 4 + r) * HEAD + tx + c * 16] = acc[r][c] * inv;
    }
}

// ---------------------------------------------------------------------------
extern "C" void kernel_launch(void* const* d_in, const int* in_sizes, int n_in,
                              void* d_out, int out_size)
{
    const float* x  = (const float*)d_in[0];
    const float* Wk = (const float*)d_in[1];
    const float* Wq = (const float*)d_in[2];
    const float* Wv = (const float*)d_in[3];
    float* out = (float*)d_out;

    // QKV projection: grid (16384/64, 1, 3)
    qkv_proj<<<dim3(MTOT / 64, 1, 3), 256>>>(x, Wq, Wk, Wv);

    // Flash attention
    cudaFuncSetAttribute(flash_attn, cudaFuncAttributeMaxDynamicSharedMemorySize, FA_SMEM);
    flash_attn<<<dim3(SEQ / BM, BATCH), 256, FA_SMEM>>>(out);
}

// round 2
// speedup vs baseline: 3.6856x; 3.6856x over previous
#include <cuda_runtime.h>
#include <math.h>

#define EMBED 1024
#define HEAD  128
#define BATCH 8
#define SEQ   2048
#define MTOT  (BATCH*SEQ)

// Scratch for Q/K/V projections (allocation-free: __device__ globals).
__device__ float g_q[MTOT * HEAD];
__device__ float g_k[MTOT * HEAD];
__device__ float g_v[MTOT * HEAD];

// ---------------------------------------------------------------------------
// helpers: tf32 round + m16n8k8 tf32 mma
// ---------------------------------------------------------------------------
__device__ __forceinline__ unsigned tf32u(float x) {
    unsigned u;
    asm("cvt.rna.tf32.f32 %0, %1;" : "=r"(u) : "f"(x));
    return u;
}
__device__ __forceinline__ float tf32f(float x) {
    return __uint_as_float(tf32u(x));
}
__device__ __forceinline__ void mma_tf32(float d[4],
                                         unsigned a0, unsigned a1, unsigned a2, unsigned a3,
                                         unsigned b0, unsigned b1) {
    asm volatile(
        "mma.sync.aligned.m16n8k8.row.col.f32.tf32.tf32.f32 "
        "{%0,%1,%2,%3}, {%4,%5,%6,%7}, {%8,%9}, {%0,%1,%2,%3};"
        : "+f"(d[0]), "+f"(d[1]), "+f"(d[2]), "+f"(d[3])
        : "r"(a0), "r"(a1), "r"(a2), "r"(a3), "r"(b0), "r"(b1));
}

// ---------------------------------------------------------------------------
// Kernel A: fused QKV projection via tf32 mma.
// CTA tile 128x128 (full N), 4 warps in 2x2 grid, warp tile 64x64.
// Xs stride 36 (=4 mod 32: A-frag reads conflict-free), Ws stride 136 (=8 mod 32).
// ---------------------------------------------------------------------------
__global__ __launch_bounds__(128) void qkv_mma(
    const float* __restrict__ x,
    const float* __restrict__ Wq,
    const float* __restrict__ Wk,
    const float* __restrict__ Wv)
{
    __shared__ float Xs[128 * 36];
    __shared__ float Ws[32 * 136];

    const float* W   = (blockIdx.z == 0) ? Wq : (blockIdx.z == 1) ? Wk : Wv;
    float*       out = (blockIdx.z == 0) ? g_q : (blockIdx.z == 1) ? g_k : g_v;

    const int tid  = threadIdx.x;
    const int wid  = tid >> 5;
    const int lane = tid & 31;
    const int qi   = lane >> 2;   // quad row (0..7)
    const int qj   = lane & 3;    // quad col (0..3)
    const int wm   = wid >> 1;    // warp m (0..1)
    const int wn   = wid & 1;     // warp n (0..1)
    const int m0   = blockIdx.x * 128;

    float c[4][8][4];
#pragma unroll
    for (int mt = 0; mt < 4; mt++)
#pragma unroll
        for (int nt = 0; nt < 8; nt++)
#pragma unroll
            for (int e = 0; e < 4; e++) c[mt][nt][e] = 0.f;

    for (int k0 = 0; k0 < EMBED; k0 += 32) {
        // stage X tile 128x32 (tf32-rounded)
#pragma unroll
        for (int p = 0; p < 8; p++) {
            int i = tid + p * 128;
            int row = i >> 3, c4 = i & 7;
            float4 v = *reinterpret_cast<const float4*>(
                &x[(size_t)(m0 + row) * EMBED + k0 + c4 * 4]);
            v.x = tf32f(v.x); v.y = tf32f(v.y); v.z = tf32f(v.z); v.w = tf32f(v.w);
            *reinterpret_cast<float4*>(&Xs[row * 36 + c4 * 4]) = v;
        }
        // stage W tile 32x128
#pragma unroll
        for (int p = 0; p < 8; p++) {
            int i = tid + p * 128;
            int row = i >> 5, c4 = i & 31;
            float4 v = *reinterpret_cast<const float4*>(
                &W[(size_t)(k0 + row) * HEAD + c4 * 4]);
            v.x = tf32f(v.x); v.y = tf32f(v.y); v.z = tf32f(v.z); v.w = tf32f(v.w);
            *reinterpret_cast<float4*>(&Ws[row * 136 + c4 * 4]) = v;
        }
        __syncthreads();

#pragma unroll
        for (int ks = 0; ks < 4; ks++) {
            unsigned a[4][4];
#pragma unroll
            for (int mt = 0; mt < 4; mt++) {
                int rb = wm * 64 + mt * 16;
                int kk = ks * 8 + qj;
                a[mt][0] = __float_as_uint(Xs[(rb + qi) * 36 + kk]);
                a[mt][1] = __float_as_uint(Xs[(rb + qi + 8) * 36 + kk]);
                a[mt][2] = __float_as_uint(Xs[(rb + qi) * 36 + kk + 4]);
                a[mt][3] = __float_as_uint(Xs[(rb + qi + 8) * 36 + kk + 4]);
            }
#pragma unroll
            for (int nt = 0; nt < 8; nt++) {
                int nb = wn * 64 + nt * 8 + qi;
                unsigned b0 = __float_as_uint(Ws[(ks * 8 + qj) * 136 + nb]);
                unsigned b1 = __float_as_uint(Ws[(ks * 8 + qj + 4) * 136 + nb]);
#pragma unroll
                for (int mt = 0; mt < 4; mt++)
                    mma_tf32(c[mt][nt], a[mt][0], a[mt][1], a[mt][2], a[mt][3], b0, b1);
            }
        }
        __syncthreads();
    }

    // epilogue: float2 stores
#pragma unroll
    for (int mt = 0; mt < 4; mt++) {
        int r0 = m0 + wm * 64 + mt * 16 + qi;
#pragma unroll
        for (int nt = 0; nt < 8; nt++) {
            int col = wn * 64 + nt * 8 + 2 * qj;
            *reinterpret_cast<float2*>(&out[(size_t)r0 * HEAD + col]) =
                make_float2(c[mt][nt][0], c[mt][nt][1]);
            *reinterpret_cast<float2*>(&out[(size_t)(r0 + 8) * HEAD + col]) =
                make_float2(c[mt][nt][2], c[mt][nt][3]);
        }
    }
}

// ---------------------------------------------------------------------------
// Kernel B: flash attention via tf32 mma.
// BM=64, BN=64, 4 warps, warp = m16 x full n (softmax warp-local).
// Q held in registers as pre-scaled tf32 A-fragments (no Qs smem).
// Ks stride 132 (=4 mod 32), Vs stride 136 (=8 mod 32), Ps stride 68 (=4 mod 32).
// ---------------------------------------------------------------------------
#define KSTR 132
#define VSTR 136
#define PSTR 68
#define FA_SMEM ((64 * KSTR + 64 * VSTR + 64 * PSTR) * (int)sizeof(float))

__global__ __launch_bounds__(128) void flash_mma(float* __restrict__ out)
{
    extern __shared__ float sm[];
    float* Ks = sm;                 // 64 x 132
    float* Vs = Ks + 64 * KSTR;     // 64 x 136
    float* Ps = Vs + 64 * VSTR;     // 64 x 68

    const int tid  = threadIdx.x;
    const int wid  = tid >> 5;
    const int lane = tid & 31;
    const int qi   = lane >> 2;
    const int qj   = lane & 3;
    const int qt   = blockIdx.x;    // query tile (0..31)
    const int b    = blockIdx.y;
    const int q0   = qt * 64;
    const int m0   = wid * 16;      // warp's row base within tile

    // Load Q fragments: pre-scaled by 1/sqrt(1024)=1/32, tf32-rounded. 64 regs.
    unsigned qa[16][4];
    {
        const float* qb = g_q + ((size_t)b * SEQ + q0 + m0) * HEAD;
#pragma unroll
        for (int ks = 0; ks < 16; ks++) {
            int k = ks * 8 + qj;
            qa[ks][0] = tf32u(qb[(size_t)qi * HEAD + k] * 0.03125f);
            qa[ks][1] = tf32u(qb[(size_t)(qi + 8) * HEAD + k] * 0.03125f);
            qa[ks][2] = tf32u(qb[(size_t)qi * HEAD + k + 4] * 0.03125f);
            qa[ks][3] = tf32u(qb[(size_t)(qi + 8) * HEAD + k + 4] * 0.03125f);
        }
    }

    float o[16][4];
#pragma unroll
    for (int nt = 0; nt < 16; nt++)
#pragma unroll
        for (int e = 0; e < 4; e++) o[nt][e] = 0.f;
    float mx0 = -INFINITY, mx1 = -INFINITY, l0 = 0.f, l1 = 0.f;

    const int r0g = q0 + m0 + qi;       // global q row for c0/c1
    const int r1g = r0g + 8;            // for c2/c3

    for (int kt = 0; kt <= qt; kt++) {
        __syncthreads();
        // stage K,V tiles (64x128 each), tf32-rounded
        {
            const float* kb = g_k + ((size_t)b * SEQ + kt * 64) * HEAD;
            const float* vb = g_v + ((size_t)b * SEQ + kt * 64) * HEAD;
#pragma unroll
            for (int p = 0; p < 16; p++) {
                int i = tid + p * 128;
                int row = i >> 5, c4 = i & 31;
                float4 kv = *reinterpret_cast<const float4*>(&kb[(size_t)row * HEAD + c4 * 4]);
                kv.x = tf32f(kv.x); kv.y = tf32f(kv.y); kv.z = tf32f(kv.z); kv.w = tf32f(kv.w);
                *reinterpret_cast<float4*>(&Ks[row * KSTR + c4 * 4]) = kv;
                float4 vv = *reinterpret_cast<const float4*>(&vb[(size_t)row * HEAD + c4 * 4]);
                vv.x = tf32f(vv.x); vv.y = tf32f(vv.y); vv.z = tf32f(vv.z); vv.w = tf32f(vv.w);
                *reinterpret_cast<float4*>(&Vs[row * VSTR + c4 * 4]) = vv;
            }
        }
        __syncthreads();

        // S = Q * K^T : warp m16 x n64 (8 n-tiles), A from registers
        float s[8][4];
#pragma unroll
        for (int nt = 0; nt < 8; nt++)
#pragma unroll
            for (int e = 0; e < 4; e++) s[nt][e] = 0.f;

#pragma unroll
        for (int ks = 0; ks < 16; ks++) {
            int kk = ks * 8 + qj;
#pragma unroll
            for (int nt = 0; nt < 8; nt++) {
                int kv = nt * 8 + qi;
                unsigned b0 = __float_as_uint(Ks[kv * KSTR + kk]);
                unsigned b1 = __float_as_uint(Ks[kv * KSTR + kk + 4]);
                mma_tf32(s[nt], qa[ks][0], qa[ks][1], qa[ks][2], qa[ks][3], b0, b1);
            }
        }

        // causal mask on the diagonal tile
        if (kt == qt) {
#pragma unroll
            for (int nt = 0; nt < 8; nt++) {
                int cb = kt * 64 + nt * 8 + 2 * qj;
                if (cb > r0g)     s[nt][0] = -INFINITY;
                if (cb + 1 > r0g) s[nt][1] = -INFINITY;
                if (cb > r1g)     s[nt][2] = -INFINITY;
                if (cb + 1 > r1g) s[nt][3] = -INFINITY;
            }
        }

        // online softmax (warp-local; quad = 4 lanes sharing a row)
        {
            float t0 = -INFINITY, t1 = -INFINITY;
#pragma unroll
            for (int nt = 0; nt < 8; nt++) {
                t0 = fmaxf(t0, fmaxf(s[nt][0], s[nt][1]));
                t1 = fmaxf(t1, fmaxf(s[nt][2], s[nt][3]));
            }
            t0 = fmaxf(t0, __shfl_xor_sync(0xffffffffu, t0, 1));
            t0 = fmaxf(t0, __shfl_xor_sync(0xffffffffu, t0, 2));
            t1 = fmaxf(t1, __shfl_xor_sync(0xffffffffu, t1, 1));
            t1 = fmaxf(t1, __shfl_xor_sync(0xffffffffu, t1, 2));

            float mn0 = fmaxf(mx0, t0), mn1 = fmaxf(mx1, t1);
            float cr0 = __expf(mx0 - mn0), cr1 = __expf(mx1 - mn1);
            mx0 = mn0; mx1 = mn1;

            float rs0 = 0.f, rs1 = 0.f;
#pragma unroll
            for (int nt = 0; nt < 8; nt++) {
                s[nt][0] = __expf(s[nt][0] - mn0);
                s[nt][1] = __expf(s[nt][1] - mn0);
                s[nt][2] = __expf(s[nt][2] - mn1);
                s[nt][3] = __expf(s[nt][3] - mn1);
                rs0 += s[nt][0] + s[nt][1];
                rs1 += s[nt][2] + s[nt][3];
            }
            rs0 += __shfl_xor_sync(0xffffffffu, rs0, 1);
            rs0 += __shfl_xor_sync(0xffffffffu, rs0, 2);
            rs1 += __shfl_xor_sync(0xffffffffu, rs1, 1);
            rs1 += __shfl_xor_sync(0xffffffffu, rs1, 2);

            l0 = l0 * cr0 + rs0;
            l1 = l1 * cr1 + rs1;
#pragma unroll
            for (int nt = 0; nt < 16; nt++) {
                o[nt][0] *= cr0; o[nt][1] *= cr0;
                o[nt][2] *= cr1; o[nt][3] *= cr1;
            }
        }

        // P -> smem (tf32), warp-local rows
#pragma unroll
        for (int nt = 0; nt < 8; nt++) {
            int col = nt * 8 + 2 * qj;
            *reinterpret_cast<float2*>(&Ps[(m0 + qi) * PSTR + col]) =
                make_float2(__uint_as_float(tf32u(s[nt][0])), __uint_as_float(tf32u(s[nt][1])));
            *reinterpret_cast<float2*>(&Ps[(m0 + qi + 8) * PSTR + col]) =
                make_float2(__uint_as_float(tf32u(s[nt][2])), __uint_as_float(tf32u(s[nt][3])));
        }
        __syncwarp();

        // O += P * V : k = 64 (8 k-steps), n = 128 (16 n-tiles)
#pragma unroll
        for (int ks = 0; ks < 8; ks++) {
            int kk = ks * 8 + qj;
            unsigned p0 = __float_as_uint(Ps[(m0 + qi) * PSTR + kk]);
            unsigned p1 = __float_as_uint(Ps[(m0 + qi + 8) * PSTR + kk]);
            unsigned p2 = __float_as_uint(Ps[(m0 + qi) * PSTR + kk + 4]);
            unsigned p3 = __float_as_uint(Ps[(m0 + qi + 8) * PSTR + kk + 4]);
#pragma unroll
            for (int nt = 0; nt < 16; nt++) {
                int h = nt * 8 + qi;
                unsigned b0 = __float_as_uint(Vs[kk * VSTR + h]);
                unsigned b1 = __float_as_uint(Vs[(kk + 4) * VSTR + h]);
                mma_tf32(o[nt], p0, p1, p2, p3, b0, b1);
            }
        }
    }

    // epilogue
    {
        float inv0 = 1.f / l0, inv1 = 1.f / l1;
        float* ob = out + ((size_t)b * SEQ) * HEAD;
#pragma unroll
        for (int nt = 0; nt < 16; nt++) {
            int col = nt * 8 + 2 * qj;
            *reinterpret_cast<float2*>(&ob[(size_t)r0g * HEAD + col]) =
                make_float2(o[nt][0] * inv0, o[nt][1] * inv0);
            *reinterpret_cast<float2*>(&ob[(size_t)r1g * HEAD + col]) =
                make_float2(o[nt][2] * inv1, o[nt][3] * inv1);
        }
    }
}

// ---------------------------------------------------------------------------
extern "C" void kernel_launch(void* const* d_in, const int* in_sizes, int n_in,
                              void* d_out, int out_size)
{
    const float* x  = (const float*)d_in[0];
    const float* Wk = (const float*)d_in[1];
    const float* Wq = (const float*)d_in[2];
    const float* Wv = (const float*)d_in[3];
    float* out = (float*)d_out;

    qkv_mma<<<dim3(MTOT / 128, 1, 3), 128>>>(x, Wq, Wk, Wv);

    cudaFuncSetAttribute(flash_mma, cudaFuncAttributeMaxDynamicSharedMemorySize, FA_SMEM);
    flash_mma<<<dim3(SEQ / 64, BATCH), 128, FA_SMEM>>>(out);
}

// round 3
// speedup vs baseline: 4.8848x; 1.3254x over previous
#include <cuda_runtime.h>
#include <math.h>

#define EMBED 1024
#define HEAD  128
#define BATCH 8
#define SEQ   2048
#define MTOT  (BATCH*SEQ)

// Scratch (allocation-free: __device__ globals). Values stored tf32-rounded.
__device__ float g_q[MTOT * HEAD];   // pre-scaled by 1/32
__device__ float g_k[MTOT * HEAD];
__device__ float g_v[MTOT * HEAD];
// W pre-permuted+tf32: [z][k-chunk][16 row-pairs][264] (row-pair interleaved)
__device__ float g_wp[3][32][16 * 264];

// ---------------------------------------------------------------------------
// helpers
// ---------------------------------------------------------------------------
__device__ __forceinline__ unsigned tf32u(float x) {
    unsigned u; asm("cvt.rna.tf32.f32 %0, %1;" : "=r"(u) : "f"(x)); return u;
}
__device__ __forceinline__ float tf32f(float x) { return __uint_as_float(tf32u(x)); }

__device__ __forceinline__ void mma_tf32(float d[4],
                                         unsigned a0, unsigned a1, unsigned a2, unsigned a3,
                                         unsigned b0, unsigned b1) {
    asm volatile(
        "mma.sync.aligned.m16n8k8.row.col.f32.tf32.tf32.f32 "
        "{%0,%1,%2,%3}, {%4,%5,%6,%7}, {%8,%9}, {%0,%1,%2,%3};"
        : "+f"(d[0]), "+f"(d[1]), "+f"(d[2]), "+f"(d[3])
        : "r"(a0), "r"(a1), "r"(a2), "r"(a3), "r"(b0), "r"(b1));
}
__device__ __forceinline__ void ldsm4(unsigned m[4], unsigned saddr) {
    asm volatile("ldmatrix.sync.aligned.m8n8.x4.shared.b16 {%0,%1,%2,%3}, [%4];"
                 : "=r"(m[0]), "=r"(m[1]), "=r"(m[2]), "=r"(m[3]) : "r"(saddr));
}
__device__ __forceinline__ void cpasync16(unsigned dst, const void* src) {
    asm volatile("cp.async.ca.shared.global [%0], [%1], 16;" :: "r"(dst), "l"(src));
}
#define CP_COMMIT asm volatile("cp.async.commit_group;")
#define CP_WAIT0  asm volatile("cp.async.wait_group 0;" ::: "memory")

// ---------------------------------------------------------------------------
// Prep: permute + tf32-round W into g_wp.
// Row-pair layout: k -> (pr = (k%32/8)*4 + k%4, half = (k%8)/4), col = 2*n + half
// ---------------------------------------------------------------------------
__global__ void w_prep(const float* __restrict__ Wq,
                       const float* __restrict__ Wk,
                       const float* __restrict__ Wv)
{
    int z = blockIdx.y;
    const float* W = (z == 0) ? Wq : (z == 1) ? Wk : Wv;
    int i = blockIdx.x * 256 + threadIdx.x;
    if (i >= EMBED * HEAD) return;
    int k = i >> 7, n = i & 127;
    int c = k >> 5, kk = k & 31;
    int pr = ((kk >> 3) << 2) + (kk & 3), hf = (kk >> 2) & 1;
    g_wp[z][c][pr * 264 + 2 * n + hf] = tf32f(W[(size_t)k * HEAD + n]);
}

// ---------------------------------------------------------------------------
// Kernel A: QKV projection. 256 threads, 8 warps (4m x 2n), warp tile m32 x n64.
// A-frags via ldmatrix (Xs row-major, stride 36). B-frags via LDS.64 on the
// row-pair interleaved Ws tile (cp.async'd straight from g_wp, no cvt).
// ---------------------------------------------------------------------------
__global__ __launch_bounds__(256, 2) void qkv_mma(const float* __restrict__ x)
{
    __shared__ float Xs[128 * 36];
    __shared__ float Ws[16 * 264];

    const int z = blockIdx.z;
    float* out = (z == 0) ? g_q : (z == 1) ? g_k : g_v;
    const float oscale = (z == 0) ? 0.03125f : 1.0f;   // fold 1/sqrt(1024) into Q

    const int tid = threadIdx.x;
    const int wid = tid >> 5, lane = tid & 31;
    const int qi = lane >> 2, qj = lane & 3;
    const int g  = lane >> 3, r = lane & 7;
    const int wm = wid >> 1, wn = wid & 1;
    const int m0 = blockIdx.x * 128;

    const unsigned XsB = (unsigned)__cvta_generic_to_shared(Xs);
    const unsigned WsB = (unsigned)__cvta_generic_to_shared(Ws);

    float c[2][8][4];
#pragma unroll
    for (int mt = 0; mt < 2; mt++)
#pragma unroll
        for (int nt = 0; nt < 8; nt++)
#pragma unroll
            for (int e = 0; e < 4; e++) c[mt][nt][e] = 0.f;

    const float* xbase = x + (size_t)m0 * EMBED;

    for (int k0 = 0; k0 < EMBED; k0 += 32) {
        // W tile: straight cp.async copy of 16*264 floats (1056 x 16B)
        const float4* wsrc = (const float4*)&g_wp[z][k0 >> 5][0];
#pragma unroll
        for (int p = 0; p < 5; p++) {
            int i = tid + p * 256;
            if (i < 1056) cpasync16(WsB + i * 16, wsrc + i);
        }
        // X tile 128x32, tf32-rounded, row-major stride 36
#pragma unroll
        for (int p = 0; p < 4; p++) {
            int i = tid + p * 256;
            int row = i >> 3, c4 = i & 7;
            float4 v = *reinterpret_cast<const float4*>(
                &xbase[(size_t)row * EMBED + k0 + c4 * 4]);
            v.x = tf32f(v.x); v.y = tf32f(v.y); v.z = tf32f(v.z); v.w = tf32f(v.w);
            *reinterpret_cast<float4*>(&Xs[row * 36 + c4 * 4]) = v;
        }
        CP_COMMIT; CP_WAIT0;
        __syncthreads();

#pragma unroll
        for (int ks = 0; ks < 4; ks++) {
            unsigned a[2][4];
#pragma unroll
            for (int mt = 0; mt < 2; mt++)
                ldsm4(a[mt], XsB + (unsigned)((wm * 32 + mt * 16 + (g & 1) * 8 + r) * 144
                                              + ks * 32 + (g >> 1) * 16));
#pragma unroll
            for (int nt = 0; nt < 8; nt++) {
                float2 bv = *reinterpret_cast<const float2*>(
                    &Ws[(ks * 4 + qj) * 264 + 2 * (wn * 64 + nt * 8 + qi)]);
                unsigned b0 = __float_as_uint(bv.x), b1 = __float_as_uint(bv.y);
                mma_tf32(c[0][nt], a[0][0], a[0][1], a[0][2], a[0][3], b0, b1);
                mma_tf32(c[1][nt], a[1][0], a[1][1], a[1][2], a[1][3], b0, b1);
            }
        }
        __syncthreads();
    }

    // epilogue: tf32-round (and scale Q); float2 stores
#pragma unroll
    for (int mt = 0; mt < 2; mt++) {
        int r0 = m0 + wm * 32 + mt * 16 + qi;
#pragma unroll
        for (int nt = 0; nt < 8; nt++) {
            int col = wn * 64 + nt * 8 + 2 * qj;
            *reinterpret_cast<float2*>(&out[(size_t)r0 * HEAD + col]) =
                make_float2(tf32f(c[mt][nt][0] * oscale), tf32f(c[mt][nt][1] * oscale));
            *reinterpret_cast<float2*>(&out[(size_t)(r0 + 8) * HEAD + col]) =
                make_float2(tf32f(c[mt][nt][2] * oscale), tf32f(c[mt][nt][3] * oscale));
        }
    }
}

// ---------------------------------------------------------------------------
// Kernel B: flash attention. BM=BN=64, 4 warps (warp m16 x n64 for QK).
// Q-frags in regs (ldmatrix'd once from a staging pass through Ks).
// K: cp.async row-major stride 132, B-frags via ldmatrix.x4 (2 n-tiles/instr).
// V: row-pair interleaved [32][264], B-frags via LDS.64.
// P: row-major stride 68, A-frags via ldmatrix.x4.
// Schedule: heavy-first, bid and bid+148 (same SM) get complementary tiles.
// ---------------------------------------------------------------------------
#define FA_SMEM (21248 * 4)   // Ks 64*132 + Vp 32*264 + Ps 64*68 floats

__global__ __launch_bounds__(128, 2) void flash_mma(float* __restrict__ out)
{
    extern __shared__ float sm[];
    float* Ks = sm;               // 64 x 132 (row-major)
    float* Vp = sm + 8448;        // 32 x 264 (row-pair interleaved)
    float* Ps = sm + 16896;       // 64 x 68  (row-major)
    const unsigned KsB = (unsigned)__cvta_generic_to_shared(Ks);
    const unsigned PsB = (unsigned)__cvta_generic_to_shared(Ps);

    const int tid = threadIdx.x;
    const int wid = tid >> 5, lane = tid & 31;
    const int qi = lane >> 2, qj = lane & 3;
    const int g  = lane >> 3, r = lane & 7;

    // balanced heavy-first schedule
    const int bid = blockIdx.x;
    const int t  = (bid < 148) ? bid : 403 - bid;
    const int qt = 31 - (t >> 3);
    const int b  = t & 7;
    const int q0 = qt * 64;
    const int m0 = wid * 16;

    // ---- stage Q through Ks, ldmatrix into regs (g_q is pre-scaled tf32) ----
    {
        const float* qb = g_q + ((size_t)b * SEQ + q0) * HEAD;
#pragma unroll
        for (int p = 0; p < 16; p++) {
            int i = tid + p * 128;
            int row = i >> 5, c4 = i & 31;
            cpasync16(KsB + (unsigned)(row * 528 + c4 * 16), qb + (size_t)row * HEAD + c4 * 4);
        }
        CP_COMMIT; CP_WAIT0;
        __syncthreads();
    }
    unsigned qa[16][4];
    {
        const unsigned aOff = (unsigned)((m0 + (g & 1) * 8 + r) * 528 + (g >> 1) * 16);
#pragma unroll
        for (int ks = 0; ks < 16; ks++) ldsm4(qa[ks], KsB + aOff + ks * 32);
    }

    float o[16][4];
#pragma unroll
    for (int nt = 0; nt < 16; nt++)
#pragma unroll
        for (int e = 0; e < 4; e++) o[nt][e] = 0.f;
    float mx0 = -INFINITY, mx1 = -INFINITY, l0 = 0.f, l1 = 0.f;

    const int r0g = q0 + m0 + qi;
    const int r1g = r0g + 8;

    const unsigned bOff = (unsigned)(((g >> 1) * 8 + r) * 528 + (g & 1) * 16);
    const unsigned pOff = (unsigned)((m0 + (g & 1) * 8 + r) * 272 + (g >> 1) * 16);
    const float* vfrag = &Vp[qj * 264 + 2 * qi];

    for (int kt = 0; kt <= qt; kt++) {
        __syncthreads();   // prior QK/PV reads (and Q-frag ldmatrix) done
        {
            const float* kb = g_k + ((size_t)b * SEQ + kt * 64) * HEAD;
            const float* vb = g_v + ((size_t)b * SEQ + kt * 64) * HEAD;
#pragma unroll
            for (int p = 0; p < 16; p++) {
                int i = tid + p * 128;
                int row = i >> 5, c4 = i & 31;
                cpasync16(KsB + (unsigned)(row * 528 + c4 * 16),
                          kb + (size_t)row * HEAD + c4 * 4);
            }
#pragma unroll
            for (int p = 0; p < 16; p++) {
                int i = tid + p * 128;
                int row = i >> 5, c4 = i & 31;
                float4 vv = *reinterpret_cast<const float4*>(&vb[(size_t)row * HEAD + c4 * 4]);
                int pr = ((row >> 3) << 2) + (row & 3), hf = (row >> 2) & 1;
                float* vd = &Vp[pr * 264 + 8 * c4 + hf];
                vd[0] = vv.x; vd[2] = vv.y; vd[4] = vv.z; vd[6] = vv.w;
            }
            CP_COMMIT; CP_WAIT0;
        }
        __syncthreads();

        // ---- S = Q K^T : 16 k-steps, ldmatrix.x4 covers 2 n-tiles ----
        float s[8][4];
#pragma unroll
        for (int nt = 0; nt < 8; nt++)
#pragma unroll
            for (int e = 0; e < 4; e++) s[nt][e] = 0.f;

#pragma unroll
        for (int ks = 0; ks < 16; ks++) {
#pragma unroll
            for (int np = 0; np < 4; np++) {
                unsigned bm[4];
                ldsm4(bm, KsB + bOff + (unsigned)(np * 8448 + ks * 32));
                mma_tf32(s[2 * np],     qa[ks][0], qa[ks][1], qa[ks][2], qa[ks][3], bm[0], bm[1]);
                mma_tf32(s[2 * np + 1], qa[ks][0], qa[ks][1], qa[ks][2], qa[ks][3], bm[2], bm[3]);
            }
        }

        // causal mask on the diagonal tile
        if (kt == qt) {
#pragma unroll
            for (int nt = 0; nt < 8; nt++) {
                int cb = kt * 64 + nt * 8 + 2 * qj;
                if (cb > r0g)     s[nt][0] = -INFINITY;
                if (cb + 1 > r0g) s[nt][1] = -INFINITY;
                if (cb > r1g)     s[nt][2] = -INFINITY;
                if (cb + 1 > r1g) s[nt][3] = -INFINITY;
            }
        }

        // ---- online softmax (quad-local rows) ----
        {
            float t0 = -INFINITY, t1 = -INFINITY;
#pragma unroll
            for (int nt = 0; nt < 8; nt++) {
                t0 = fmaxf(t0, fmaxf(s[nt][0], s[nt][1]));
                t1 = fmaxf(t1, fmaxf(s[nt][2], s[nt][3]));
            }
            t0 = fmaxf(t0, __shfl_xor_sync(0xffffffffu, t0, 1));
            t0 = fmaxf(t0, __shfl_xor_sync(0xffffffffu, t0, 2));
            t1 = fmaxf(t1, __shfl_xor_sync(0xffffffffu, t1, 1));
            t1 = fmaxf(t1, __shfl_xor_sync(0xffffffffu, t1, 2));

            float mn0 = fmaxf(mx0, t0), mn1 = fmaxf(mx1, t1);
            float cr0 = __expf(mx0 - mn0), cr1 = __expf(mx1 - mn1);
            mx0 = mn0; mx1 = mn1;

            float rs0 = 0.f, rs1 = 0.f;
#pragma unroll
            for (int nt = 0; nt < 8; nt++) {
                s[nt][0] = __expf(s[nt][0] - mn0);
                s[nt][1] = __expf(s[nt][1] - mn0);
                s[nt][2] = __expf(s[nt][2] - mn1);
                s[nt][3] = __expf(s[nt][3] - mn1);
                rs0 += s[nt][0] + s[nt][1];
                rs1 += s[nt][2] + s[nt][3];
            }
            rs0 += __shfl_xor_sync(0xffffffffu, rs0, 1);
            rs0 += __shfl_xor_sync(0xffffffffu, rs0, 2);
            rs1 += __shfl_xor_sync(0xffffffffu, rs1, 1);
            rs1 += __shfl_xor_sync(0xffffffffu, rs1, 2);

            l0 = l0 * cr0 + rs0;
            l1 = l1 * cr1 + rs1;
#pragma unroll
            for (int nt = 0; nt < 16; nt++) {
                o[nt][0] *= cr0; o[nt][1] *= cr0;
                o[nt][2] *= cr1; o[nt][3] *= cr1;
            }
        }

        // P -> smem (tf32), row-major stride 68
#pragma unroll
        for (int nt = 0; nt < 8; nt++) {
            int col = nt * 8 + 2 * qj;
            *reinterpret_cast<float2*>(&Ps[(m0 + qi) * 68 + col]) =
                make_float2(__uint_as_float(tf32u(s[nt][0])), __uint_as_float(tf32u(s[nt][1])));
            *reinterpret_cast<float2*>(&Ps[(m0 + qi + 8) * 68 + col]) =
                make_float2(__uint_as_float(tf32u(s[nt][2])), __uint_as_float(tf32u(s[nt][3])));
        }
        __syncwarp();

        // ---- O += P V : A via ldmatrix, B via LDS.64 on paired V ----
#pragma unroll
        for (int ks = 0; ks < 8; ks++) {
            unsigned pA[4];
            ldsm4(pA, PsB + pOff + ks * 32);
#pragma unroll
            for (int nt = 0; nt < 16; nt++) {
                float2 bv = *reinterpret_cast<const float2*>(vfrag + ks * 1056 + nt * 16);
                mma_tf32(o[nt], pA[0], pA[1], pA[2], pA[3],
                         __float_as_uint(bv.x), __float_as_uint(bv.y));
            }
        }
    }

    // epilogue
    {
        float inv0 = 1.f / l0, inv1 = 1.f / l1;
        float* ob = out + ((size_t)b * SEQ) * HEAD;
#pragma unroll
        for (int nt = 0; nt < 16; nt++) {
            int col = nt * 8 + 2 * qj;
            *reinterpret_cast<float2*>(&ob[(size_t)r0g * HEAD + col]) =
                make_float2(o[nt][0] * inv0, o[nt][1] * inv0);
            *reinterpret_cast<float2*>(&ob[(size_t)r1g * HEAD + col]) =
                make_float2(o[nt][2] * inv1, o[nt][3] * inv1);
        }
    }
}

// ---------------------------------------------------------------------------
extern "C" void kernel_launch(void* const* d_in, const int* in_sizes, int n_in,
                              void* d_out, int out_size)
{
    const float* x  = (const float*)d_in[0];
    const float* Wk = (const float*)d_in[1];
    const float* Wq = (const float*)d_in[2];
    const float* Wv = (const float*)d_in[3];
    float* out = (float*)d_out;

    w_prep<<<dim3((EMBED * HEAD + 255) / 256, 3), 256>>>(Wq, Wk, Wv);
    qkv_mma<<<dim3(MTOT / 128, 1, 3), 256>>>(x);

    cudaFuncSetAttribute(flash_mma, cudaFuncAttributeMaxDynamicSharedMemorySize, FA_SMEM);
    flash_mma<<<dim3(256, 1), 128, FA_SMEM>>>(out);
}

// round 5
// speedup vs baseline: 5.5821x; 1.1428x over previous
#include <cuda_runtime.h>
#include <math.h>

#define EMBED 1024
#define HEAD  128
#define BATCH 8
#define SEQ   2048
#define MTOT  (BATCH*SEQ)

// Scratch (allocation-free). All values stored tf32-rounded.
__device__ float g_q[MTOT * HEAD];          // pre-scaled by 1/32
__device__ float g_k[MTOT * HEAD];
__device__ float g_vt[MTOT * HEAD];         // V transposed: [b][h][s]
// W pre-permuted+tf32: [z][k-chunk][16 row-pairs][264]
__device__ float g_wp[3][32][16 * 264];

// ---------------------------------------------------------------------------
// helpers
// ---------------------------------------------------------------------------
__device__ __forceinline__ unsigned tf32u(float x) {
    unsigned u; asm("cvt.rna.tf32.f32 %0, %1;" : "=r"(u) : "f"(x)); return u;
}
__device__ __forceinline__ float tf32f(float x) { return __uint_as_float(tf32u(x)); }

__device__ __forceinline__ void mma_tf32(float d[4],
                                         unsigned a0, unsigned a1, unsigned a2, unsigned a3,
                                         unsigned b0, unsigned b1) {
    asm volatile(
        "mma.sync.aligned.m16n8k8.row.col.f32.tf32.tf32.f32 "
        "{%0,%1,%2,%3}, {%4,%5,%6,%7}, {%8,%9}, {%0,%1,%2,%3};"
        : "+f"(d[0]), "+f"(d[1]), "+f"(d[2]), "+f"(d[3])
        : "r"(a0), "r"(a1), "r"(a2), "r"(a3), "r"(b0), "r"(b1));
}
__device__ __forceinline__ void ldsm4(unsigned m[4], unsigned saddr) {
    asm volatile("ldmatrix.sync.aligned.m8n8.x4.shared.b16 {%0,%1,%2,%3}, [%4];"
                 : "=r"(m[0]), "=r"(m[1]), "=r"(m[2]), "=r"(m[3]) : "r"(saddr));
}
__device__ __forceinline__ void cpasync16(unsigned dst, const void* src) {
    asm volatile("cp.async.ca.shared.global [%0], [%1], 16;" :: "r"(dst), "l"(src));
}
#define CP_COMMIT asm volatile("cp.async.commit_group;")
#define CP_WAIT0  asm volatile("cp.async.wait_group 0;" ::: "memory")
#define CP_WAIT1  asm volatile("cp.async.wait_group 1;" ::: "memory")

// ---------------------------------------------------------------------------
// Prep: permute + tf32-round W into g_wp (row-pair interleaved).
// ---------------------------------------------------------------------------
__global__ void w_prep(const float* __restrict__ Wq,
                       const float* __restrict__ Wk,
                       const float* __restrict__ Wv)
{
    int z = blockIdx.y;
    const float* W = (z == 0) ? Wq : (z == 1) ? Wk : Wv;
    int i = blockIdx.x * 256 + threadIdx.x;
    if (i >= EMBED * HEAD) return;
    int k = i >> 7, n = i & 127;
    int c = k >> 5, kk = k & 31;
    int pr = ((kk >> 3) << 2) + (kk & 3), hf = (kk >> 2) & 1;
    g_wp[z][c][pr * 264 + 2 * n + hf] = tf32f(W[(size_t)k * HEAD + n]);
}

// ---------------------------------------------------------------------------
// Kernel A: QKV projection, double-buffered. 256 threads, 8 warps (4m x 2n),
// warp tile m32 x n64. z==2 (V) output is transposed via an smem epilogue.
// ---------------------------------------------------------------------------
#define XS_F 4608            // 128*36 floats
#define WS_F 4224            // 16*264 floats
__global__ __launch_bounds__(256, 2) void qkv_mma(const float* __restrict__ x)
{
    __shared__ float smb[2 * XS_F + 2 * WS_F];   // 70656 B
    float* Xs[2] = { smb, smb + XS_F };
    float* Ws[2] = { smb + 2 * XS_F, smb + 2 * XS_F + WS_F };

    const int z = blockIdx.z;
    float* out = (z == 0) ? g_q : g_k;           // z==2 handled by transpose
    const float oscale = (z == 0) ? 0.03125f : 1.0f;

    const int tid = threadIdx.x;
    const int wid = tid >> 5, lane = tid & 31;
    const int qi = lane >> 2, qj = lane & 3;
    const int g  = lane >> 3, r = lane & 7;
    const int wm = wid >> 1, wn = wid & 1;
    const int m0 = blockIdx.x * 128;

    const unsigned SB = (unsigned)__cvta_generic_to_shared(smb);
    const unsigned XsB[2] = { SB, SB + XS_F * 4 };
    const unsigned WsB[2] = { SB + 2 * XS_F * 4, SB + 2 * XS_F * 4 + WS_F * 4 };

    float c[2][8][4];
#pragma unroll
    for (int mt = 0; mt < 2; mt++)
#pragma unroll
        for (int nt = 0; nt < 8; nt++)
#pragma unroll
            for (int e = 0; e < 4; e++) c[mt][nt][e] = 0.f;

    const float* xbase = x + (size_t)m0 * EMBED;

    // prologue: stage chunk 0 into buffer 0
    {
        const float4* wsrc = (const float4*)&g_wp[z][0][0];
#pragma unroll
        for (int p = 0; p < 5; p++) {
            int i = tid + p * 256;
            if (i < 1056) cpasync16(WsB[0] + i * 16, wsrc + i);
        }
        CP_COMMIT;
#pragma unroll
        for (int p = 0; p < 4; p++) {
            int i = tid + p * 256;
            int row = i >> 3, c4 = i & 7;
            float4 v = *reinterpret_cast<const float4*>(
                &xbase[(size_t)row * EMBED + c4 * 4]);
            v.x = tf32f(v.x); v.y = tf32f(v.y); v.z = tf32f(v.z); v.w = tf32f(v.w);
            *reinterpret_cast<float4*>(&Xs[0][row * 36 + c4 * 4]) = v;
        }
    }

    for (int ch = 0; ch < 32; ch++) {
        const int cur = ch & 1, nxt = cur ^ 1;
        CP_WAIT0;
        __syncthreads();

        float4 xr[4];
        if (ch < 31) {
            // prefetch next X into regs + next W via cp.async
            const int k0n = (ch + 1) * 32;
            const float4* wsrc = (const float4*)&g_wp[z][ch + 1][0];
#pragma unroll
            for (int p = 0; p < 5; p++) {
                int i = tid + p * 256;
                if (i < 1056) cpasync16(WsB[nxt] + i * 16, wsrc + i);
            }
            CP_COMMIT;
#pragma unroll
            for (int p = 0; p < 4; p++) {
                int i = tid + p * 256;
                int row = i >> 3, c4 = i & 7;
                xr[p] = *reinterpret_cast<const float4*>(
                    &xbase[(size_t)row * EMBED + k0n + c4 * 4]);
            }
        }

        // compute on current buffers
#pragma unroll
        for (int ks = 0; ks < 4; ks++) {
            unsigned a[2][4];
#pragma unroll
            for (int mt = 0; mt < 2; mt++)
                ldsm4(a[mt], XsB[cur] + (unsigned)((wm * 32 + mt * 16 + (g & 1) * 8 + r) * 144
                                                   + ks * 32 + (g >> 1) * 16));
#pragma unroll
            for (int nt = 0; nt < 8; nt++) {
                float2 bv = *reinterpret_cast<const float2*>(
                    &Ws[cur][(ks * 4 + qj) * 264 + 2 * (wn * 64 + nt * 8 + qi)]);
                unsigned b0 = __float_as_uint(bv.x), b1 = __float_as_uint(bv.y);
                mma_tf32(c[0][nt], a[0][0], a[0][1], a[0][2], a[0][3], b0, b1);
                mma_tf32(c[1][nt], a[1][0], a[1][1], a[1][2], a[1][3], b0, b1);
            }
        }

        if (ch < 31) {
            // tf32-round + store prefetched X into next buffer
#pragma unroll
            for (int p = 0; p < 4; p++) {
                int i = tid + p * 256;
                int row = i >> 3, c4 = i & 7;
                float4 v = xr[p];
                v.x = tf32f(v.x); v.y = tf32f(v.y); v.z = tf32f(v.z); v.w = tf32f(v.w);
                *reinterpret_cast<float4*>(&Xs[nxt][row * 36 + c4 * 4]) = v;
            }
        }
    }

    if (z < 2) {
        // direct row-major epilogue (tf32-rounded; Q pre-scaled)
#pragma unroll
        for (int mt = 0; mt < 2; mt++) {
            int r0 = m0 + wm * 32 + mt * 16 + qi;
#pragma unroll
            for (int nt = 0; nt < 8; nt++) {
                int col = wn * 64 + nt * 8 + 2 * qj;
                *reinterpret_cast<float2*>(&out[(size_t)r0 * HEAD + col]) =
                    make_float2(tf32f(c[mt][nt][0] * oscale), tf32f(c[mt][nt][1] * oscale));
                *reinterpret_cast<float2*>(&out[(size_t)(r0 + 8) * HEAD + col]) =
                    make_float2(tf32f(c[mt][nt][2] * oscale), tf32f(c[mt][nt][3] * oscale));
            }
        }
    } else {
        // V: transpose through smem, coalesced STG to g_vt[b][h][s]
        __syncthreads();                 // all compute done; reuse smem
        float* T = smb;                  // [h=128][s=128], stride 132
#pragma unroll
        for (int mt = 0; mt < 2; mt++) {
            int r0 = wm * 32 + mt * 16 + qi;
#pragma unroll
            for (int nt = 0; nt < 8; nt++) {
                int col = wn * 64 + nt * 8 + 2 * qj;
                T[col * 132 + r0]             = tf32f(c[mt][nt][0]);
                T[(col + 1) * 132 + r0]       = tf32f(c[mt][nt][1]);
                T[col * 132 + r0 + 8]         = tf32f(c[mt][nt][2]);
                T[(col + 1) * 132 + r0 + 8]   = tf32f(c[mt][nt][3]);
            }
        }
        __syncthreads();
        const int b = m0 >> 11, s0 = m0 & 2047;
#pragma unroll
        for (int p = 0; p < 16; p++) {
            int h = wid + p * 8;
            float4 v = *reinterpret_cast<const float4*>(&T[h * 132 + lane * 4]);
            *reinterpret_cast<float4*>(
                &g_vt[((size_t)b * HEAD + h) * SEQ + s0 + lane * 4]) = v;
        }
    }
}

// ---------------------------------------------------------------------------
// Kernel B: flash attention, fully pipelined cp.async.
// BM=BN=64, 4 warps (warp m16). Q-frags in regs. K row-major (stride 132),
// V from g_vt (stride 68), P row-major (stride 68); all frags via ldmatrix.
// Pipeline: V(kt) hides behind QK+softmax; K(kt+1) hides behind softmax+PV.
// ---------------------------------------------------------------------------
#define KS_F (64 * 132)
#define VT_F (128 * 68)
#define PS_F (64 * 68)
#define FA_SMEM ((KS_F + VT_F + PS_F) * 4)   // 86016 B

__global__ __launch_bounds__(128, 2) void flash_mma(float* __restrict__ out)
{
    extern __shared__ float sm[];
    float* Ks = sm;
    float* Vt = sm + KS_F;
    float* Ps = sm + KS_F + VT_F;
    const unsigned KsB = (unsigned)__cvta_generic_to_shared(Ks);
    const unsigned VtB = (unsigned)__cvta_generic_to_shared(Vt);
    const unsigned PsB = (unsigned)__cvta_generic_to_shared(Ps);

    const int tid = threadIdx.x;
    const int wid = tid >> 5, lane = tid & 31;
    const int qi = lane >> 2, qj = lane & 3;
    const int g  = lane >> 3, r = lane & 7;

    // balanced heavy-first schedule (bid and bid+148 share an SM)
    const int bid = blockIdx.x;
    const int t  = (bid < 148) ? bid : 403 - bid;
    const int qt = 31 - (t >> 3);
    const int b  = t & 7;
    const int q0 = qt * 64;
    const int m0 = wid * 16;

    const float* kbase  = g_k  + (size_t)b * SEQ * HEAD;
    const float* vtbase = g_vt + (size_t)b * HEAD * SEQ;

    // ---- stage Q through Ks, ldmatrix into regs ----
    {
        const float* qb = g_q + ((size_t)b * SEQ + q0) * HEAD;
#pragma unroll
        for (int p = 0; p < 16; p++) {
            int i = tid + p * 128;
            int row = i >> 5, c4 = i & 31;
            cpasync16(KsB + (unsigned)(row * 528 + c4 * 16), qb + (size_t)row * HEAD + c4 * 4);
        }
        CP_COMMIT; CP_WAIT0;
        __syncthreads();
    }
    unsigned qa[16][4];
    {
        const unsigned aOff = (unsigned)((m0 + (g & 1) * 8 + r) * 528 + (g >> 1) * 16);
#pragma unroll
        for (int ks = 0; ks < 16; ks++) ldsm4(qa[ks], KsB + aOff + ks * 32);
    }
    __syncthreads();   // Ks free for K(0)

    // prologue: issue K(0) then V(0)
#pragma unroll
    for (int p = 0; p < 16; p++) {
        int i = tid + p * 128;
        int row = i >> 5, c4 = i & 31;
        cpasync16(KsB + (unsigned)(row * 528 + c4 * 16), kbase + (size_t)row * HEAD + c4 * 4);
    }
    CP_COMMIT;
#pragma unroll
    for (int p = 0; p < 16; p++) {
        int i = tid + p * 128;
        int h = i >> 4, c4 = i & 15;
        cpasync16(VtB + (unsigned)(h * 272 + c4 * 16), vtbase + (size_t)h * SEQ + c4 * 4);
    }
    CP_COMMIT;

    float o[16][4];
#pragma unroll
    for (int nt = 0; nt < 16; nt++)
#pragma unroll
        for (int e = 0; e < 4; e++) o[nt][e] = 0.f;
    float mx0 = -INFINITY, mx1 = -INFINITY, l0 = 0.f, l1 = 0.f;

    const int r0g = q0 + m0 + qi;
    const int r1g = r0g + 8;

    const unsigned bOff = (unsigned)(((g >> 1) * 8 + r) * 528 + (g & 1) * 16);
    const unsigned vOff = (unsigned)(((g >> 1) * 8 + r) * 272 + (g & 1) * 16);
    const unsigned pOff = (unsigned)((m0 + (g & 1) * 8 + r) * 272 + (g >> 1) * 16);

    for (int kt = 0; kt <= qt; kt++) {
        CP_WAIT1;            // K(kt) done (V(kt) may still fly)
        __syncthreads();

        // ---- S = Q K^T ----
        float s[8][4];
#pragma unroll
        for (int nt = 0; nt < 8; nt++)
#pragma unroll
            for (int e = 0; e < 4; e++) s[nt][e] = 0.f;
#pragma unroll
        for (int ks = 0; ks < 16; ks++) {
#pragma unroll
            for (int np = 0; np < 4; np++) {
                unsigned bm[4];
                ldsm4(bm, KsB + bOff + (unsigned)(np * 8448 + ks * 32));
                mma_tf32(s[2 * np],     qa[ks][0], qa[ks][1], qa[ks][2], qa[ks][3], bm[0], bm[1]);
                mma_tf32(s[2 * np + 1], qa[ks][0], qa[ks][1], qa[ks][2], qa[ks][3], bm[2], bm[3]);
            }
        }
        __syncthreads();     // all warps done reading Ks

        // issue K(kt+1) (hides behind softmax + PV)
        if (kt < qt) {
            const float* kb = kbase + (size_t)(kt + 1) * 64 * HEAD;
#pragma unroll
            for (int p = 0; p < 16; p++) {
                int i = tid + p * 128;
                int row = i >> 5, c4 = i & 31;
                cpasync16(KsB + (unsigned)(row * 528 + c4 * 16),
                          kb + (size_t)row * HEAD + c4 * 4);
            }
        }
        CP_COMMIT;           // (empty group when kt==qt keeps wait-count invariant)

        // causal mask on the diagonal tile
        if (kt == qt) {
#pragma unroll
            for (int nt = 0; nt < 8; nt++) {
                int cb = kt * 64 + nt * 8 + 2 * qj;
                if (cb > r0g)     s[nt][0] = -INFINITY;
                if (cb + 1 > r0g) s[nt][1] = -INFINITY;
                if (cb > r1g)     s[nt][2] = -INFINITY;
                if (cb + 1 > r1g) s[nt][3] = -INFINITY;
            }
        }

        // ---- online softmax (quad-local rows) ----
        {
            float t0 = -INFINITY, t1 = -INFINITY;
#pragma unroll
            for (int nt = 0; nt < 8; nt++) {
                t0 = fmaxf(t0, fmaxf(s[nt][0], s[nt][1]));
                t1 = fmaxf(t1, fmaxf(s[nt][2], s[nt][3]));
            }
            t0 = fmaxf(t0, __shfl_xor_sync(0xffffffffu, t0, 1));
            t0 = fmaxf(t0, __shfl_xor_sync(0xffffffffu, t0, 2));
            t1 = fmaxf(t1, __shfl_xor_sync(0xffffffffu, t1, 1));
            t1 = fmaxf(t1, __shfl_xor_sync(0xffffffffu, t1, 2));

            float mn0 = fmaxf(mx0, t0), mn1 = fmaxf(mx1, t1);
            float cr0 = __expf(mx0 - mn0), cr1 = __expf(mx1 - mn1);
            mx0 = mn0; mx1 = mn1;

            float rs0 = 0.f, rs1 = 0.f;
#pragma unroll
            for (int nt = 0; nt < 8; nt++) {
                s[nt][0] = __expf(s[nt][0] - mn0);
                s[nt][1] = __expf(s[nt][1] - mn0);
                s[nt][2] = __expf(s[nt][2] - mn1);
                s[nt][3] = __expf(s[nt][3] - mn1);
                rs0 += s[nt][0] + s[nt][1];
                rs1 += s[nt][2] + s[nt][3];
            }
            rs0 += __shfl_xor_sync(0xffffffffu, rs0, 1);
            rs0 += __shfl_xor_sync(0xffffffffu, rs0, 2);
            rs1 += __shfl_xor_sync(0xffffffffu, rs1, 1);
            rs1 += __shfl_xor_sync(0xffffffffu, rs1, 2);

            l0 = l0 * cr0 + rs0;
            l1 = l1 * cr1 + rs1;
#pragma unroll
            for (int nt = 0; nt < 16; nt++) {
                o[nt][0] *= cr0; o[nt][1] *= cr0;
                o[nt][2] *= cr1; o[nt][3] *= cr1;
            }
        }

        // P -> smem (tf32)
#pragma unroll
        for (int nt = 0; nt < 8; nt++) {
            int col = nt * 8 + 2 * qj;
            *reinterpret_cast<float2*>(&Ps[(m0 + qi) * 68 + col]) =
                make_float2(__uint_as_float(tf32u(s[nt][0])), __uint_as_float(tf32u(s[nt][1])));
            *reinterpret_cast<float2*>(&Ps[(m0 + qi + 8) * 68 + col]) =
                make_float2(__uint_as_float(tf32u(s[nt][2])), __uint_as_float(tf32u(s[nt][3])));
        }

        CP_WAIT1;            // V(kt) done (K(kt+1) may still fly)
        __syncthreads();

        // ---- O += P V : both operands via ldmatrix ----
#pragma unroll
        for (int ks = 0; ks < 8; ks++) {
            unsigned pA[4];
            ldsm4(pA, PsB + pOff + ks * 32);
#pragma unroll
            for (int np = 0; np < 8; np++) {
                unsigned bm[4];
                ldsm4(bm, VtB + vOff + (unsigned)(np * 4352 + ks * 32));
                mma_tf32(o[2 * np],     pA[0], pA[1], pA[2], pA[3], bm[0], bm[1]);
                mma_tf32(o[2 * np + 1], pA[0], pA[1], pA[2], pA[3], bm[2], bm[3]);
            }
        }
        __syncthreads();     // all warps done reading Vt (and Ps)

        // issue V(kt+1)
        if (kt < qt) {
            const float* vb = vtbase + (size_t)(kt + 1) * 64;
#pragma unroll
            for (int p = 0; p < 16; p++) {
                int i = tid + p * 128;
                int h = i >> 4, c4 = i & 15;
                cpasync16(VtB + (unsigned)(h * 272 + c4 * 16),
                          vb + (size_t)h * SEQ + c4 * 4);
            }
        }
        CP_COMMIT;
    }

    // epilogue
    {
        float inv0 = 1.f / l0, inv1 = 1.f / l1;
        float* ob = out + ((size_t)b * SEQ) * HEAD;
#pragma unroll
        for (int nt = 0; nt < 16; nt++) {
            int col = nt * 8 + 2 * qj;
            *reinterpret_cast<float2*>(&ob[(size_t)r0g * HEAD + col]) =
                make_float2(o[nt][0] * inv0, o[nt][1] * inv0);
            *reinterpret_cast<float2*>(&ob[(size_t)r1g * HEAD + col]) =
                make_float2(o[nt][2] * inv1, o[nt][3] * inv1);
        }
    }
}

// ---------------------------------------------------------------------------
extern "C" void kernel_launch(void* const* d_in, const int* in_sizes, int n_in,
                              void* d_out, int out_size)
{
    const float* x  = (const float*)d_in[0];
    const float* Wk = (const float*)d_in[1];
    const float* Wq = (const float*)d_in[2];
    const float* Wv = (const float*)d_in[3];
    float* out = (float*)d_out;

    w_prep<<<dim3((EMBED * HEAD + 255) / 256, 3), 256>>>(Wq, Wk, Wv);
    qkv_mma<<<dim3(MTOT / 128, 1, 3), 256>>>(x);

    cudaFuncSetAttribute(flash_mma, cudaFuncAttributeMaxDynamicSharedMemorySize, FA_SMEM);
    flash_mma<<<dim3(256, 1), 128, FA_SMEM>>>(out);
}

// round 8
// speedup vs baseline: 7.9168x; 1.4183x over previous
#include <cuda_runtime.h>
#include <cuda_fp16.h>
#include <math.h>

#define EMBED 1024
#define HEAD  128
#define BATCH 8
#define SEQ   2048
#define MTOT  (BATCH*SEQ)

// Scratch (allocation-free). All values stored as fp16.
__device__ __half g_q[MTOT * HEAD];          // pre-scaled by 1/32
__device__ __half g_k[MTOT * HEAD];
__device__ __half g_vt[MTOT * HEAD];         // V transposed: [b][h][s]
__device__ __half g_wt[3][HEAD][EMBED];      // W^T fp16: [z][n][k]

// ---------------------------------------------------------------------------
// helpers
// ---------------------------------------------------------------------------
__device__ __forceinline__ unsigned packh2(float a, float b) {
    __half2 h = __floats2half2_rn(a, b);
    return *reinterpret_cast<unsigned*>(&h);
}
__device__ __forceinline__ void mma_f16(float d[4],
                                        unsigned a0, unsigned a1, unsigned a2, unsigned a3,
                                        unsigned b0, unsigned b1) {
    asm volatile(
        "mma.sync.aligned.m16n8k16.row.col.f32.f16.f16.f32 "
        "{%0,%1,%2,%3}, {%4,%5,%6,%7}, {%8,%9}, {%0,%1,%2,%3};"
        : "+f"(d[0]), "+f"(d[1]), "+f"(d[2]), "+f"(d[3])
        : "r"(a0), "r"(a1), "r"(a2), "r"(a3), "r"(b0), "r"(b1));
}
__device__ __forceinline__ void ldsm4(unsigned m[4], unsigned saddr) {
    asm volatile("ldmatrix.sync.aligned.m8n8.x4.shared.b16 {%0,%1,%2,%3}, [%4];"
                 : "=r"(m[0]), "=r"(m[1]), "=r"(m[2]), "=r"(m[3]) : "r"(saddr));
}
__device__ __forceinline__ void cpasync16(unsigned dst, const void* src) {
    asm volatile("cp.async.ca.shared.global [%0], [%1], 16;" :: "r"(dst), "l"(src));
}
#define CP_COMMIT asm volatile("cp.async.commit_group;")
#define CP_WAIT0  asm volatile("cp.async.wait_group 0;" ::: "memory")
#define CP_WAIT1  asm volatile("cp.async.wait_group 1;" ::: "memory")

// ---------------------------------------------------------------------------
// Prep: transpose + fp16-round W into g_wt[z][n][k].
// ---------------------------------------------------------------------------
__global__ void w_prep(const float* __restrict__ Wq,
                       const float* __restrict__ Wk,
                       const float* __restrict__ Wv)
{
    int z = blockIdx.y;
    const float* W = (z == 0) ? Wq : (z == 1) ? Wk : Wv;
    int i = blockIdx.x * 256 + threadIdx.x;     // i = k*128 + n
    if (i >= EMBED * HEAD) return;
    int k = i >> 7, n = i & 127;
    g_wt[z][n][k] = __float2half_rn(W[i]);
}

// ---------------------------------------------------------------------------
// Kernel A: QKV projection (fp16 mma, m16n8k16), double-buffered.
// 256 threads, 8 warps (4m x 2n), warp tile m32 x n64, K-chunk 32 (2 k-steps).
// z==2 (V) output transposed via smem epilogue.
// ---------------------------------------------------------------------------
#define XS_H (128 * 40)
#define WS_H (128 * 40)
__global__ __launch_bounds__(256, 2) void qkv_mma(const float* __restrict__ x)
{
    __shared__ __half smh[2 * XS_H + 2 * WS_H];   // 40960 B
    __half* Xs[2] = { smh, smh + XS_H };

    const int z = blockIdx.z;
    __half* out = (z == 0) ? g_q : g_k;          // z==2 via transpose path
    const float oscale = (z == 0) ? 0.03125f : 1.0f;

    const int tid = threadIdx.x;
    const int wid = tid >> 5, lane = tid & 31;
    const int qi = lane >> 2, qj = lane & 3;
    const int g  = lane >> 3, r = lane & 7;
    const int l16 = lane & 15, hi16 = lane >> 4;
    const int wm = wid >> 1, wn = wid & 1;
    const int m0 = blockIdx.x * 128;

    const unsigned SB = (unsigned)__cvta_generic_to_shared(smh);
    const unsigned XsB[2] = { SB, SB + XS_H * 2 };
    const unsigned WtB[2] = { SB + 2 * XS_H * 2, SB + 2 * XS_H * 2 + WS_H * 2 };

    float c[2][8][4];
#pragma unroll
    for (int mt = 0; mt < 2; mt++)
#pragma unroll
        for (int nt = 0; nt < 8; nt++)
#pragma unroll
            for (int e = 0; e < 4; e++) c[mt][nt][e] = 0.f;

    const float* xbase = x + (size_t)m0 * EMBED;

    // prologue: stage chunk 0
    {
#pragma unroll
        for (int p = 0; p < 2; p++) {
            int i = tid + p * 256;
            int row = i >> 2, c4 = i & 3;
            cpasync16(WtB[0] + (unsigned)(row * 80 + c4 * 16),
                      &g_wt[z][row][c4 * 8]);
        }
        CP_COMMIT;
#pragma unroll
        for (int p = 0; p < 4; p++) {
            int i = tid + p * 256;
            int row = i >> 3, c4 = i & 7;
            float4 v = *reinterpret_cast<const float4*>(
                &xbase[(size_t)row * EMBED + c4 * 4]);
            uint2 u = make_uint2(packh2(v.x, v.y), packh2(v.z, v.w));
            *reinterpret_cast<uint2*>(&Xs[0][row * 40 + c4 * 4]) = u;
        }
    }

    for (int ch = 0; ch < 32; ch++) {
        const int cur = ch & 1, nxt = cur ^ 1;
        CP_WAIT0;
        __syncthreads();

        float4 xr[4];
        if (ch < 31) {
            const int k0n = (ch + 1) * 32;
#pragma unroll
            for (int p = 0; p < 2; p++) {
                int i = tid + p * 256;
                int row = i >> 2, c4 = i & 3;
                cpasync16(WtB[nxt] + (unsigned)(row * 80 + c4 * 16),
                          &g_wt[z][row][k0n + c4 * 8]);
            }
            CP_COMMIT;
#pragma unroll
            for (int p = 0; p < 4; p++) {
                int i = tid + p * 256;
                int row = i >> 3, c4 = i & 7;
                xr[p] = *reinterpret_cast<const float4*>(
                    &xbase[(size_t)row * EMBED + k0n + c4 * 4]);
            }
        }

        // compute: 2 k16 steps
#pragma unroll
        for (int ks = 0; ks < 2; ks++) {
            unsigned a[2][4];
#pragma unroll
            for (int mt = 0; mt < 2; mt++)
                ldsm4(a[mt], XsB[cur] + (unsigned)((wm * 32 + mt * 16 + l16) * 80
                                                   + hi16 * 16 + ks * 32));
#pragma unroll
            for (int np = 0; np < 4; np++) {
                unsigned bm[4];
                ldsm4(bm, WtB[cur] + (unsigned)(((g >> 1) * 8 + r + wn * 64 + np * 16) * 80
                                                + (g & 1) * 16 + ks * 32));
                mma_f16(c[0][2 * np],     a[0][0], a[0][1], a[0][2], a[0][3], bm[0], bm[1]);
                mma_f16(c[0][2 * np + 1], a[0][0], a[0][1], a[0][2], a[0][3], bm[2], bm[3]);
                mma_f16(c[1][2 * np],     a[1][0], a[1][1], a[1][2], a[1][3], bm[0], bm[1]);
                mma_f16(c[1][2 * np + 1], a[1][0], a[1][1], a[1][2], a[1][3], bm[2], bm[3]);
            }
        }

        if (ch < 31) {
#pragma unroll
            for (int p = 0; p < 4; p++) {
                int i = tid + p * 256;
                int row = i >> 3, c4 = i & 7;
                uint2 u = make_uint2(packh2(xr[p].x, xr[p].y), packh2(xr[p].z, xr[p].w));
                *reinterpret_cast<uint2*>(&Xs[nxt][row * 40 + c4 * 4]) = u;
            }
        }
    }

    if (z < 2) {
        // fp16 stores (Q pre-scaled by 1/32)
#pragma unroll
        for (int mt = 0; mt < 2; mt++) {
            int r0 = m0 + wm * 32 + mt * 16 + qi;
#pragma unroll
            for (int nt = 0; nt < 8; nt++) {
                int col = wn * 64 + nt * 8 + 2 * qj;
                *reinterpret_cast<unsigned*>(&out[(size_t)r0 * HEAD + col]) =
                    packh2(c[mt][nt][0] * oscale, c[mt][nt][1] * oscale);
                *reinterpret_cast<unsigned*>(&out[(size_t)(r0 + 8) * HEAD + col]) =
                    packh2(c[mt][nt][2] * oscale, c[mt][nt][3] * oscale);
            }
        }
    } else {
        // V: transpose through smem -> g_vt[b][h][s] (fp16)
        __syncthreads();
        __half* T = smh;                 // [h=128][s=128], stride 136 halves
#pragma unroll
        for (int mt = 0; mt < 2; mt++) {
            int r0 = wm * 32 + mt * 16 + qi;
#pragma unroll
            for (int nt = 0; nt < 8; nt++) {
                int col = wn * 64 + nt * 8 + 2 * qj;
                T[col * 136 + r0]           = __float2half_rn(c[mt][nt][0]);
                T[(col + 1) * 136 + r0]     = __float2half_rn(c[mt][nt][1]);
                T[col * 136 + r0 + 8]       = __float2half_rn(c[mt][nt][2]);
                T[(col + 1) * 136 + r0 + 8] = __float2half_rn(c[mt][nt][3]);
            }
        }
        __syncthreads();
        // 32 lanes x 4 halves (uint2) = exactly 128 s-values per h-row
        const int b = m0 >> 11, s0 = m0 & 2047;
#pragma unroll
        for (int p = 0; p < 16; p++) {
            int h = wid + p * 8;
            uint2 v = *reinterpret_cast<const uint2*>(&T[h * 136 + lane * 4]);
            *reinterpret_cast<uint2*>(
                &g_vt[((size_t)b * HEAD + h) * SEQ + s0 + lane * 4]) = v;
        }
    }
}

// ---------------------------------------------------------------------------
// Kernel B: flash attention (fp16 mma), fully pipelined cp.async.
// BM=BN=64, 4 warps (warp m16). Q-frags in regs (8 k16 steps).
// Ks stride 136 halves (272 B), Vt 72 halves (144 B), Ps 72 halves.
// ---------------------------------------------------------------------------
#define KS_H (64 * 136)
#define VT_H (128 * 72)
#define PS_H (64 * 72)
#define FA_SMEM ((KS_H + VT_H + PS_H) * 2)   // 45056 B

__global__ __launch_bounds__(128, 2) void flash_mma(float* __restrict__ out)
{
    extern __shared__ __half smf[];
    const unsigned SB = (unsigned)__cvta_generic_to_shared(smf);
    __half* Ps = smf + KS_H + VT_H;
    const unsigned KsB = SB;
    const unsigned VtB = SB + KS_H * 2;
    const unsigned PsB = SB + (KS_H + VT_H) * 2;

    const int tid = threadIdx.x;
    const int wid = tid >> 5, lane = tid & 31;
    const int qi = lane >> 2, qj = lane & 3;
    const int g  = lane >> 3, r = lane & 7;
    const int l16 = lane & 15, hi16 = lane >> 4;

    // balanced heavy-first schedule (bid and bid+148 share an SM)
    const int bid = blockIdx.x;
    const int t  = (bid < 148) ? bid : 403 - bid;
    const int qt = 31 - (t >> 3);
    const int b  = t & 7;
    const int q0 = qt * 64;
    const int m0 = wid * 16;

    const __half* kbase  = g_k  + (size_t)b * SEQ * HEAD;
    const __half* vtbase = g_vt + (size_t)b * HEAD * SEQ;

    // ---- stage Q through Ks, ldmatrix into regs ----
    {
        const __half* qb = g_q + ((size_t)b * SEQ + q0) * HEAD;
#pragma unroll
        for (int p = 0; p < 8; p++) {
            int i = tid + p * 128;
            int row = i >> 4, c4 = i & 15;
            cpasync16(KsB + (unsigned)(row * 272 + c4 * 16), qb + (size_t)row * HEAD + c4 * 8);
        }
        CP_COMMIT; CP_WAIT0;
        __syncthreads();
    }
    unsigned qa[8][4];
    {
        const unsigned aOff = (unsigned)((m0 + l16) * 272 + hi16 * 16);
#pragma unroll
        for (int ks = 0; ks < 8; ks++) ldsm4(qa[ks], KsB + aOff + ks * 32);
    }
    __syncthreads();   // Ks free for K(0)

    // prologue: issue K(0) then V(0)
#pragma unroll
    for (int p = 0; p < 8; p++) {
        int i = tid + p * 128;
        int row = i >> 4, c4 = i & 15;
        cpasync16(KsB + (unsigned)(row * 272 + c4 * 16), kbase + (size_t)row * HEAD + c4 * 8);
    }
    CP_COMMIT;
#pragma unroll
    for (int p = 0; p < 8; p++) {
        int i = tid + p * 128;
        int h = i >> 3, c4 = i & 7;
        cpasync16(VtB + (unsigned)(h * 144 + c4 * 16), vtbase + (size_t)h * SEQ + c4 * 8);
    }
    CP_COMMIT;

    float o[16][4];
#pragma unroll
    for (int nt = 0; nt < 16; nt++)
#pragma unroll
        for (int e = 0; e < 4; e++) o[nt][e] = 0.f;
    float mx0 = -INFINITY, mx1 = -INFINITY, l0 = 0.f, l1 = 0.f;

    const int r0g = q0 + m0 + qi;
    const int r1g = r0g + 8;

    const unsigned bOff = (unsigned)(((g >> 1) * 8 + r) * 272 + (g & 1) * 16);
    const unsigned vOff = (unsigned)(((g >> 1) * 8 + r) * 144 + (g & 1) * 16);
    const unsigned pOff = (unsigned)((m0 + l16) * 144 + hi16 * 16);

    for (int kt = 0; kt <= qt; kt++) {
        CP_WAIT1;            // K(kt) done (V(kt) may still fly)
        __syncthreads();

        // ---- S = Q K^T : 8 k16 steps ----
        float s[8][4];
#pragma unroll
        for (int nt = 0; nt < 8; nt++)
#pragma unroll
            for (int e = 0; e < 4; e++) s[nt][e] = 0.f;
#pragma unroll
        for (int ks = 0; ks < 8; ks++) {
#pragma unroll
            for (int np = 0; np < 4; np++) {
                unsigned bm[4];
                ldsm4(bm, KsB + bOff + (unsigned)(np * 4352 + ks * 32));
                mma_f16(s[2 * np],     qa[ks][0], qa[ks][1], qa[ks][2], qa[ks][3], bm[0], bm[1]);
                mma_f16(s[2 * np + 1], qa[ks][0], qa[ks][1], qa[ks][2], qa[ks][3], bm[2], bm[3]);
            }
        }
        __syncthreads();     // all warps done reading Ks

        // issue K(kt+1) (hides behind softmax + PV)
        if (kt < qt) {
            const __half* kb = kbase + (size_t)(kt + 1) * 64 * HEAD;
#pragma unroll
            for (int p = 0; p < 8; p++) {
                int i = tid + p * 128;
                int row = i >> 4, c4 = i & 15;
                cpasync16(KsB + (unsigned)(row * 272 + c4 * 16),
                          kb + (size_t)row * HEAD + c4 * 8);
            }
        }
        CP_COMMIT;

        // causal mask on the diagonal tile
        if (kt == qt) {
#pragma unroll
            for (int nt = 0; nt < 8; nt++) {
                int cb = kt * 64 + nt * 8 + 2 * qj;
                if (cb > r0g)     s[nt][0] = -INFINITY;
                if (cb + 1 > r0g) s[nt][1] = -INFINITY;
                if (cb > r1g)     s[nt][2] = -INFINITY;
                if (cb + 1 > r1g) s[nt][3] = -INFINITY;
            }
        }

        // ---- online softmax (quad-local rows) ----
        {
            float t0 = -INFINITY, t1 = -INFINITY;
#pragma unroll
            for (int nt = 0; nt < 8; nt++) {
                t0 = fmaxf(t0, fmaxf(s[nt][0], s[nt][1]));
                t1 = fmaxf(t1, fmaxf(s[nt][2], s[nt][3]));
            }
            t0 = fmaxf(t0, __shfl_xor_sync(0xffffffffu, t0, 1));
            t0 = fmaxf(t0, __shfl_xor_sync(0xffffffffu, t0, 2));
            t1 = fmaxf(t1, __shfl_xor_sync(0xffffffffu, t1, 1));
            t1 = fmaxf(t1, __shfl_xor_sync(0xffffffffu, t1, 2));

            float mn0 = fmaxf(mx0, t0), mn1 = fmaxf(mx1, t1);
            float cr0 = __expf(mx0 - mn0), cr1 = __expf(mx1 - mn1);
            mx0 = mn0; mx1 = mn1;

            float rs0 = 0.f, rs1 = 0.f;
#pragma unroll
            for (int nt = 0; nt < 8; nt++) {
                s[nt][0] = __expf(s[nt][0] - mn0);
                s[nt][1] = __expf(s[nt][1] - mn0);
                s[nt][2] = __expf(s[nt][2] - mn1);
                s[nt][3] = __expf(s[nt][3] - mn1);
                rs0 += s[nt][0] + s[nt][1];
                rs1 += s[nt][2] + s[nt][3];
            }
            rs0 += __shfl_xor_sync(0xffffffffu, rs0, 1);
            rs0 += __shfl_xor_sync(0xffffffffu, rs0, 2);
            rs1 += __shfl_xor_sync(0xffffffffu, rs1, 1);
            rs1 += __shfl_xor_sync(0xffffffffu, rs1, 2);

            l0 = l0 * cr0 + rs0;
            l1 = l1 * cr1 + rs1;
#pragma unroll
            for (int nt = 0; nt < 16; nt++) {
                o[nt][0] *= cr0; o[nt][1] *= cr0;
                o[nt][2] *= cr1; o[nt][3] *= cr1;
            }
        }

        // P -> smem (fp16)
#pragma unroll
        for (int nt = 0; nt < 8; nt++) {
            int col = nt * 8 + 2 * qj;
            *reinterpret_cast<unsigned*>(&Ps[(m0 + qi) * 72 + col]) =
                packh2(s[nt][0], s[nt][1]);
            *reinterpret_cast<unsigned*>(&Ps[(m0 + qi + 8) * 72 + col]) =
                packh2(s[nt][2], s[nt][3]);
        }

        CP_WAIT1;            // V(kt) done (K(kt+1) may still fly)
        __syncthreads();

        // ---- O += P V : 4 k16 steps ----
#pragma unroll
        for (int ks = 0; ks < 4; ks++) {
            unsigned pA[4];
            ldsm4(pA, PsB + pOff + ks * 32);
#pragma unroll
            for (int np = 0; np < 8; np++) {
                unsigned bm[4];
                ldsm4(bm, VtB + vOff + (unsigned)(np * 2304 + ks * 32));
                mma_f16(o[2 * np],     pA[0], pA[1], pA[2], pA[3], bm[0], bm[1]);
                mma_f16(o[2 * np + 1], pA[0], pA[1], pA[2], pA[3], bm[2], bm[3]);
            }
        }
        __syncthreads();     // all warps done reading Vt (and Ps)

        // issue V(kt+1)
        if (kt < qt) {
            const __half* vb = vtbase + (size_t)(kt + 1) * 64;
#pragma unroll
            for (int p = 0; p < 8; p++) {
                int i = tid + p * 128;
                int h = i >> 3, c4 = i & 7;
                cpasync16(VtB + (unsigned)(h * 144 + c4 * 16),
                          vb + (size_t)h * SEQ + c4 * 8);
            }
        }
        CP_COMMIT;
    }

    // epilogue (fp32 out)
    {
        float inv0 = 1.f / l0, inv1 = 1.f / l1;
        float* ob = out + ((size_t)b * SEQ) * HEAD;
#pragma unroll
        for (int nt = 0; nt < 16; nt++) {
            int col = nt * 8 + 2 * qj;
            *reinterpret_cast<float2*>(&ob[(size_t)r0g * HEAD + col]) =
                make_float2(o[nt][0] * inv0, o[nt][1] * inv0);
            *reinterpret_cast<float2*>(&ob[(size_t)r1g * HEAD + col]) =
                make_float2(o[nt][2] * inv1, o[nt][3] * inv1);
        }
    }
}

// ---------------------------------------------------------------------------
extern "C" void kernel_launch(void* const* d_in, const int* in_sizes, int n_in,
                              void* d_out, int out_size)
{
    const float* x  = (const float*)d_in[0];
    const float* Wk = (const float*)d_in[1];
    const float* Wq = (const float*)d_in[2];
    const float* Wv = (const float*)d_in[3];
    float* out = (float*)d_out;

    w_prep<<<dim3((EMBED * HEAD + 255) / 256, 3), 256>>>(Wq, Wk, Wv);
    qkv_mma<<<dim3(MTOT / 128, 1, 3), 256>>>(x);

    cudaFuncSetAttribute(flash_mma, cudaFuncAttributeMaxDynamicSharedMemorySize, FA_SMEM);
    flash_mma<<<dim3(256, 1), 128, FA_SMEM>>>(out);
}